// round 1
// baseline (speedup 1.0000x reference)
#include <cuda_runtime.h>
#include <math.h>

#define HH 32
#define T_STEPS 20
#define NEGV -1e9f

__device__ __forceinline__ float sigf(float x) {
    return 1.0f / (1.0f + expf(-x));
}
__device__ __forceinline__ float tanh_fast(float x) {
    // tanh(x) = 2*sigmoid(2x) - 1
    return 2.0f / (1.0f + expf(-2.0f * x)) - 1.0f;
}

__global__ __launch_bounds__(128, 1)
void controller_kernel(const float* __restrict__ w_ih,
                       const float* __restrict__ w_hh,
                       const float* __restrict__ b_ih,
                       const float* __restrict__ b_hh,
                       const float* __restrict__ g_emb,
                       const float* __restrict__ emb_kernel,
                       const float* __restrict__ emb_down,
                       const float* __restrict__ emb_up,
                       const float* __restrict__ w_kernel,
                       const float* __restrict__ w_down,
                       const float* __restrict__ w_up,
                       const float* __restrict__ noise,
                       float* __restrict__ out,
                       int out_size) {
    // Transposed weights: Wt[k][r]  (k: 0..31 -> w_ih col k, 32..63 -> w_hh col k-32)
    __shared__ float Wt[64][128];
    __shared__ float bias[128];
    __shared__ float xh[64];      // xh[0..31] = x, xh[32..63] = h
    __shared__ float cst[32];     // cell state
    __shared__ float gates[128];
    __shared__ float logits[8];
    __shared__ int   s_sh;

    const int tid = threadIdx.x;

    // Load weights transposed (each thread handles 32 rows-worth spread out)
    for (int idx = tid; idx < 128 * 32; idx += 128) {
        const int r = idx >> 5;      // row 0..127
        const int k = idx & 31;      // col 0..31
        Wt[k][r]      = w_ih[idx];
        Wt[k + 32][r] = w_hh[idx];
    }
    bias[tid] = b_ih[tid] + b_hh[tid];
    if (tid < 32) {
        xh[tid]      = g_emb[tid];  // x0 = g_emb[0]
        xh[32 + tid] = 0.0f;        // h0
        cst[tid]     = 0.0f;        // c0
    }

    float lp_sum = 0.0f, ent_sum = 0.0f;
    float samples_f[T_STEPS];

    __syncthreads();

    for (int t = 0; t < T_STEPS; ++t) {
        // ---- gates = W_ih x + W_hh h + (b_ih + b_hh), one row per thread ----
        float acc = bias[tid];
#pragma unroll
        for (int k = 0; k < 64; ++k) {
            acc = fmaf(Wt[k][tid], xh[k], acc);
        }
        gates[tid] = acc;
        __syncthreads();

        // ---- cell update: warp 0, lane j = state index ----
        if (tid < 32) {
            const float ig = gates[tid];
            const float fg = gates[tid + 32];
            const float gg = gates[tid + 64];
            const float og = gates[tid + 96];
            float c = sigf(fg) * cst[tid] + sigf(ig) * tanh_fast(gg);
            cst[tid] = c;
            xh[32 + tid] = sigf(og) * tanh_fast(c);
        }
        __syncwarp();

        // ---- phase-dependent projection / embedding tables ----
        const float* proj;
        const float* emb;
        int nvalid;
        if (t < 14)      { proj = w_kernel; emb = emb_kernel; nvalid = 8; }
        else if (t < 17) { proj = w_down;   emb = emb_down;   nvalid = 3; }
        else             { proj = w_up;     emb = emb_up;     nvalid = 3; }

        // ---- logits: threads 0..7 ----
        if (tid < 8) {
            float l = NEGV;
            if (tid < nvalid) {
                l = 0.0f;
#pragma unroll
                for (int k = 0; k < 32; ++k)
                    l = fmaf(proj[tid * 32 + k], xh[32 + k], l);
            }
            logits[tid] = l;
        }
        __syncwarp();

        // ---- softmax / gumbel argmax / entropy: thread 0 (serial, 8 elems) ----
        if (tid == 0) {
            float m = logits[0];
#pragma unroll
            for (int j = 1; j < 8; ++j) m = fmaxf(m, logits[j]);
            float se = 0.0f;
#pragma unroll
            for (int j = 0; j < 8; ++j) se += expf(logits[j] - m);
            const float lse = m + logf(se);

            // Gumbel-max sample (masked logits are -1e9, never win)
            int   s    = 0;
            float best = -1e30f;
#pragma unroll
            for (int j = 0; j < 8; ++j) {
                const float u = noise[t * 8 + j];
                const float g = -logf(-logf(u * (1.0f - 1e-6f) + 1e-7f));
                const float v = logits[j] + g;
                if (v > best) { best = v; s = j; }
            }

            float ent = 0.0f;
            for (int j = 0; j < nvalid; ++j) {
                const float lpj = logits[j] - lse;
                ent -= expf(lpj) * lpj;
            }
            lp_sum  += logits[s] - lse;
            ent_sum += ent;
            samples_f[t] = (float)s;
            s_sh = s;
        }
        __syncwarp();

        // ---- x_{t+1} = emb[s] ----
        if (tid < 32) {
            xh[tid] = emb[s_sh * 32 + tid];
        }
        __syncthreads();   // publish xh to all warps before next matvec
    }

    if (tid == 0) {
        out[0] = lp_sum;
        out[1] = ent_sum;
        for (int t = 0; t < T_STEPS && (2 + t) < out_size; ++t)
            out[2 + t] = samples_f[t];
    }
}

extern "C" void kernel_launch(void* const* d_in, const int* in_sizes, int n_in,
                              void* d_out, int out_size) {
    const float* w_ih       = (const float*)d_in[0];
    const float* w_hh       = (const float*)d_in[1];
    const float* b_ih       = (const float*)d_in[2];
    const float* b_hh       = (const float*)d_in[3];
    const float* g_emb      = (const float*)d_in[4];
    const float* emb_kernel = (const float*)d_in[5];
    const float* emb_down   = (const float*)d_in[6];
    const float* emb_up     = (const float*)d_in[7];
    const float* w_kernel   = (const float*)d_in[8];
    const float* w_down     = (const float*)d_in[9];
    const float* w_up       = (const float*)d_in[10];
    const float* noise      = (const float*)d_in[11];
    float* out = (float*)d_out;

    controller_kernel<<<1, 128>>>(w_ih, w_hh, b_ih, b_hh, g_emb,
                                  emb_kernel, emb_down, emb_up,
                                  w_kernel, w_down, w_up, noise,
                                  out, out_size);
}

// round 2
// speedup vs baseline: 2.5261x; 2.5261x over previous
#include <cuda_runtime.h>
#include <math.h>

#define T_STEPS 20
#define NEGV -1e9f
#define FULL 0xffffffffu

__device__ __forceinline__ float fsig(float x) {
    // 1/(1+e^-x) via MUFU
    return __fdividef(1.0f, 1.0f + __expf(-x));
}
__device__ __forceinline__ float ftanh(float x) {
    // tanh(x) = 1 - 2/(e^{2x}+1)
    return 1.0f - __fdividef(2.0f, __expf(2.0f * x) + 1.0f);
}

__global__ __launch_bounds__(128, 1)
void controller_kernel(const float* __restrict__ w_ih,
                       const float* __restrict__ w_hh,
                       const float* __restrict__ b_ih,
                       const float* __restrict__ b_hh,
                       const float* __restrict__ g_emb,
                       const float* __restrict__ emb_kernel,
                       const float* __restrict__ emb_down,
                       const float* __restrict__ emb_up,
                       const float* __restrict__ w_kernel,
                       const float* __restrict__ w_down,
                       const float* __restrict__ w_up,
                       const float* __restrict__ noise,
                       float* __restrict__ out,
                       int out_size) {
    __shared__ __align__(16) float xh[64];          // [0..31]=x, [32..63]=h
    __shared__ float gates[128];
    __shared__ float gsh[160];                      // precomputed gumbels
    __shared__ __align__(16) float projsh[3][8 * 36]; // padded stride 36
    __shared__ float embsh[3][8 * 32];

    const int tid = threadIdx.x;

    // ---- weights for row `tid` into registers (8 x float4) ----
    float wr[64];
    {
        const float4* wi4 = (const float4*)w_ih;
        const float4* wh4 = (const float4*)w_hh;
#pragma unroll
        for (int i = 0; i < 8; ++i) {
            float4 a = wi4[tid * 8 + i];
            wr[4 * i + 0] = a.x; wr[4 * i + 1] = a.y;
            wr[4 * i + 2] = a.z; wr[4 * i + 3] = a.w;
            float4 b = wh4[tid * 8 + i];
            wr[32 + 4 * i + 0] = b.x; wr[32 + 4 * i + 1] = b.y;
            wr[32 + 4 * i + 2] = b.z; wr[32 + 4 * i + 3] = b.w;
        }
    }
    const float bias = b_ih[tid] + b_hh[tid];

    // ---- shared-table init ----
    // zero padded proj buffers
    for (int i = tid; i < 3 * 8 * 36; i += 128)
        ((float*)projsh)[i] = 0.0f;
    __syncthreads();
    // proj tables (row-padded to stride 36)
    for (int i = tid; i < 8 * 32; i += 128)
        projsh[0][(i >> 5) * 36 + (i & 31)] = w_kernel[i];
    for (int i = tid; i < 3 * 32; i += 128) {
        projsh[1][(i >> 5) * 36 + (i & 31)] = w_down[i];
        projsh[2][(i >> 5) * 36 + (i & 31)] = w_up[i];
    }
    // emb tables
    for (int i = tid; i < 8 * 32; i += 128)
        embsh[0][i] = emb_kernel[i];
    for (int i = tid; i < 3 * 32; i += 128) {
        embsh[1][i] = emb_down[i];
        embsh[2][i] = emb_up[i];
    }
    // gumbels (accurate logf — off the critical path)
    for (int i = tid; i < T_STEPS * 8; i += 128) {
        float u = noise[i];
        gsh[i] = -logf(-logf(u * (1.0f - 1e-6f) + 1e-7f));
    }
    if (tid < 32) {
        xh[tid]      = g_emb[tid];
        xh[32 + tid] = 0.0f;
    }

    float c = 0.0f;                 // cell state (warp 0 lane tid)
    float lp_sum = 0.0f, ent_sum = 0.0f;

    __syncthreads();

    for (int t = 0; t < T_STEPS; ++t) {
        // ================= matvec: gates[tid] =================
        float a0 = bias, a1 = 0.0f, a2 = 0.0f, a3 = 0.0f;
        const float4* x4 = (const float4*)xh;
#pragma unroll
        for (int i = 0; i < 16; ++i) {
            float4 v = x4[i];
            a0 = fmaf(wr[4 * i + 0], v.x, a0);
            a1 = fmaf(wr[4 * i + 1], v.y, a1);
            a2 = fmaf(wr[4 * i + 2], v.z, a2);
            a3 = fmaf(wr[4 * i + 3], v.w, a3);
        }
        gates[tid] = (a0 + a1) + (a2 + a3);
        __syncthreads();

        // ================= tail: warp 0 only =================
        if (tid < 32) {
            const int j = tid;
            // LSTM cell
            const float gi = gates[j];
            const float gf = gates[j + 32];
            const float gg = gates[j + 64];
            const float go = gates[j + 96];
            c = fsig(gf) * c + fsig(gi) * ftanh(gg);
            xh[32 + j] = fsig(go) * ftanh(c);
            __syncwarp();

            // phase
            int ph, nvalid;
            if (t < 14)      { ph = 0; nvalid = 8; }
            else if (t < 17) { ph = 1; nvalid = 3; }
            else             { ph = 2; nvalid = 3; }

            // logits: lane j handles class a=j&7, segment seg=j>>3 (8 h-elems)
            const int a = j & 7, seg = j >> 3;
            const float* pr = &projsh[ph][a * 36 + seg * 8];
            const float* hp = &xh[32 + seg * 8];
            float4 p0 = *(const float4*)(pr);
            float4 p1 = *(const float4*)(pr + 4);
            float4 h0 = *(const float4*)(hp);
            float4 h1 = *(const float4*)(hp + 4);
            float part = p0.x * h0.x + p0.y * h0.y + p0.z * h0.z + p0.w * h0.w
                       + p1.x * h1.x + p1.y * h1.y + p1.z * h1.z + p1.w * h1.w;
            part += __shfl_xor_sync(FULL, part, 8);
            part += __shfl_xor_sync(FULL, part, 16);
            float logit = (a < nvalid) ? part : NEGV;

            // combined max / gumbel-argmax reduce over the 8 classes
            float m = logit;
            float v = logit + gsh[t * 8 + a];
            int   s = a;
#pragma unroll
            for (int o = 1; o < 8; o <<= 1) {
                float m2 = __shfl_xor_sync(FULL, m, o);
                float v2 = __shfl_xor_sync(FULL, v, o);
                int   s2 = __shfl_xor_sync(FULL, s, o);
                m = fmaxf(m, m2);
                if (v2 > v || (v2 == v && s2 < s)) { v = v2; s = s2; }
            }

            // softmax sums (each aligned 8-lane group holds every class once)
            const float d  = logit - m;
            float se  = __expf(d);
            float ss1 = se * d;
#pragma unroll
            for (int o = 1; o < 8; o <<= 1) {
                se  += __shfl_xor_sync(FULL, se,  o);
                ss1 += __shfl_xor_sync(FULL, ss1, o);
            }
            const float logit_s = __shfl_sync(FULL, logit, s);
            const float lse_r   = __logf(se);
            lp_sum  += logit_s - m - lse_r;
            ent_sum += lse_r - __fdividef(ss1, se);

            if (j == 0) out[2 + t] = (float)s;

            // next input x = emb[s]
            xh[j] = embsh[ph][s * 32 + j];
        }
        __syncthreads();
    }

    if (tid == 0) {
        out[0] = lp_sum;
        out[1] = ent_sum;
    }
}

extern "C" void kernel_launch(void* const* d_in, const int* in_sizes, int n_in,
                              void* d_out, int out_size) {
    const float* w_ih       = (const float*)d_in[0];
    const float* w_hh       = (const float*)d_in[1];
    const float* b_ih       = (const float*)d_in[2];
    const float* b_hh       = (const float*)d_in[3];
    const float* g_emb      = (const float*)d_in[4];
    const float* emb_kernel = (const float*)d_in[5];
    const float* emb_down   = (const float*)d_in[6];
    const float* emb_up     = (const float*)d_in[7];
    const float* w_kernel   = (const float*)d_in[8];
    const float* w_down     = (const float*)d_in[9];
    const float* w_up       = (const float*)d_in[10];
    const float* noise      = (const float*)d_in[11];
    float* out = (float*)d_out;

    controller_kernel<<<1, 128>>>(w_ih, w_hh, b_ih, b_hh, g_emb,
                                  emb_kernel, emb_down, emb_up,
                                  w_kernel, w_down, w_up, noise,
                                  out, out_size);
}

// round 3
// speedup vs baseline: 2.5308x; 1.0019x over previous
#include <cuda_runtime.h>
#include <math.h>

#define T_STEPS 20
#define NEGV -1e9f
#define FULL 0xffffffffu

__device__ __forceinline__ float fsig(float x) {
    return __fdividef(1.0f, 1.0f + __expf(-x));
}
__device__ __forceinline__ float ftanh(float x) {
    return 1.0f - __fdividef(2.0f, __expf(2.0f * x) + 1.0f);
}

__global__ __launch_bounds__(128, 1)
void controller_kernel(const float* __restrict__ w_ih,
                       const float* __restrict__ w_hh,
                       const float* __restrict__ b_ih,
                       const float* __restrict__ b_hh,
                       const float* __restrict__ g_emb,
                       const float* __restrict__ emb_kernel,
                       const float* __restrict__ emb_down,
                       const float* __restrict__ emb_up,
                       const float* __restrict__ w_kernel,
                       const float* __restrict__ w_down,
                       const float* __restrict__ w_up,
                       const float* __restrict__ noise,
                       float* __restrict__ out,
                       int out_size) {
    __shared__ __align__(16) float xh[64];            // [0..31]=x, [32..63]=h
    __shared__ float act[128];                        // pre-activated gates
    __shared__ float gsh[160];                        // precomputed gumbels
    __shared__ __align__(16) float projsh[3][8 * 36]; // padded stride 36
    __shared__ float embsh[3][8 * 32];

    const int tid = threadIdx.x;

    // ---- weights for gate-row `tid` into registers ----
    float wr[64];
    {
        const float4* wi4 = (const float4*)w_ih;
        const float4* wh4 = (const float4*)w_hh;
#pragma unroll
        for (int i = 0; i < 8; ++i) {
            float4 a = wi4[tid * 8 + i];
            wr[4 * i + 0] = a.x; wr[4 * i + 1] = a.y;
            wr[4 * i + 2] = a.z; wr[4 * i + 3] = a.w;
            float4 b = wh4[tid * 8 + i];
            wr[32 + 4 * i + 0] = b.x; wr[32 + 4 * i + 1] = b.y;
            wr[32 + 4 * i + 2] = b.z; wr[32 + 4 * i + 3] = b.w;
        }
    }
    const float bias = b_ih[tid] + b_hh[tid];

    // ---- shared-table init ----
    for (int i = tid; i < 3 * 8 * 36; i += 128)
        ((float*)projsh)[i] = 0.0f;
    __syncthreads();
    for (int i = tid; i < 8 * 32; i += 128)
        projsh[0][(i >> 5) * 36 + (i & 31)] = w_kernel[i];
    for (int i = tid; i < 3 * 32; i += 128) {
        projsh[1][(i >> 5) * 36 + (i & 31)] = w_down[i];
        projsh[2][(i >> 5) * 36 + (i & 31)] = w_up[i];
    }
    for (int i = tid; i < 8 * 32; i += 128)
        embsh[0][i] = emb_kernel[i];
    for (int i = tid; i < 3 * 32; i += 128) {
        embsh[1][i] = emb_down[i];
        embsh[2][i] = emb_up[i];
    }
    // gumbels: accurate logf, parallel, off the recurrence path
    for (int i = tid; i < T_STEPS * 8; i += 128) {
        float u = noise[i];
        gsh[i] = -logf(-logf(u * (1.0f - 1e-6f) + 1e-7f));
    }
    if (tid < 32) {
        xh[tid]      = g_emb[tid];
        xh[32 + tid] = 0.0f;
    }

    float c = 0.0f;                 // cell state (warp 0, lane = state idx)
    float lp_sum = 0.0f, ent_sum = 0.0f;
    const bool is_sig = (tid < 64) || (tid >= 96);  // warp-uniform

    __syncthreads();

    for (int t = 0; t < T_STEPS; ++t) {
        // ---- matvec (all 128 threads, one gate row each) ----
        float a0 = bias, a1 = 0.0f, a2 = 0.0f, a3 = 0.0f;
        const float4* x4 = (const float4*)xh;
#pragma unroll
        for (int i = 0; i < 16; ++i) {
            float4 v = x4[i];
            a0 = fmaf(wr[4 * i + 0], v.x, a0);
            a1 = fmaf(wr[4 * i + 1], v.y, a1);
            a2 = fmaf(wr[4 * i + 2], v.z, a2);
            a3 = fmaf(wr[4 * i + 3], v.w, a3);
        }
        float gacc = (a0 + a1) + (a2 + a3);
        // pre-activation in parallel (σ for i,f,o rows; tanh for g rows)
        act[tid] = is_sig ? fsig(gacc) : ftanh(gacc);

        if (tid >= 32) {
            // producers: publish gates, never block on it; wait for next xh
            asm volatile("bar.arrive 0, 128;" ::: "memory");
            asm volatile("bar.sync 1, 128;"   ::: "memory");
        } else {
            asm volatile("bar.sync 0, 128;"   ::: "memory");
            // ================= warp-0 tail =================
            const int j = tid;
            const int a   = j & 7;
            const int seg = j >> 3;
            const float gl = gsh[t * 8 + a];

            const float ai = act[j];
            const float af = act[j + 32];
            const float ag = act[j + 64];
            const float ao = act[j + 96];
            c = fmaf(af, c, ai * ag);
            xh[32 + j] = ao * ftanh(c);
            __syncwarp();

            int ph, nvalid;
            if (t < 14)      { ph = 0; nvalid = 8; }
            else if (t < 17) { ph = 1; nvalid = 3; }
            else             { ph = 2; nvalid = 3; }

            // logits: lane handles class a, h-segment seg
            const float* pr = &projsh[ph][a * 36 + seg * 8];
            const float* hp = &xh[32 + seg * 8];
            float4 p0 = *(const float4*)(pr);
            float4 p1 = *(const float4*)(pr + 4);
            float4 h0 = *(const float4*)(hp);
            float4 h1 = *(const float4*)(hp + 4);
            float part = p0.x * h0.x + p0.y * h0.y + p0.z * h0.z + p0.w * h0.w
                       + p1.x * h1.x + p1.y * h1.y + p1.z * h1.z + p1.w * h1.w;
            part += __shfl_xor_sync(FULL, part, 8);
            part += __shfl_xor_sync(FULL, part, 16);
            const float logit = (a < nvalid) ? part : NEGV;

            // merged reduce: gumbel-max, Σe^l, Σe^l·l  (no max-shift needed:
            // |valid logit| <= ~3.3; masked: e^-1e9 = +0, 0*-1e9 = -0)
            float v   = logit + gl;
            float se  = __expf(logit);
            float ss1 = se * logit;
            float vm  = v;
#pragma unroll
            for (int o = 1; o < 8; o <<= 1) {
                vm  = fmaxf(vm, __shfl_xor_sync(FULL, vm, o));
                se  += __shfl_xor_sync(FULL, se,  o);
                ss1 += __shfl_xor_sync(FULL, ss1, o);
            }
            const unsigned bal = __ballot_sync(FULL, v == vm);
            const int s = (__ffs(bal) - 1) & 7;   // lowest index on tie

            const float logit_s = __shfl_sync(FULL, logit, s);
            const float lse = __logf(se);
            lp_sum  += logit_s - lse;
            ent_sum += lse - __fdividef(ss1, se);

            if (j == 0) out[2 + t] = (float)s;

            // next input x = emb[s]
            xh[j] = embsh[ph][s * 32 + j];
            __syncwarp();
            asm volatile("bar.arrive 1, 128;" ::: "memory");
        }
    }

    if (tid == 0) {
        out[0] = lp_sum;
        out[1] = ent_sum;
    }
}

extern "C" void kernel_launch(void* const* d_in, const int* in_sizes, int n_in,
                              void* d_out, int out_size) {
    const float* w_ih       = (const float*)d_in[0];
    const float* w_hh       = (const float*)d_in[1];
    const float* b_ih       = (const float*)d_in[2];
    const float* b_hh       = (const float*)d_in[3];
    const float* g_emb      = (const float*)d_in[4];
    const float* emb_kernel = (const float*)d_in[5];
    const float* emb_down   = (const float*)d_in[6];
    const float* emb_up     = (const float*)d_in[7];
    const float* w_kernel   = (const float*)d_in[8];
    const float* w_down     = (const float*)d_in[9];
    const float* w_up       = (const float*)d_in[10];
    const float* noise      = (const float*)d_in[11];
    float* out = (float*)d_out;

    controller_kernel<<<1, 128>>>(w_ih, w_hh, b_ih, b_hh, g_emb,
                                  emb_kernel, emb_down, emb_up,
                                  w_kernel, w_down, w_up, noise,
                                  out, out_size);
}

// round 5
// speedup vs baseline: 2.5644x; 1.0133x over previous
#include <cuda_runtime.h>
#include <math.h>

#define T_STEPS 20
#define NEGV -1e9f
#define FULL 0xffffffffu

__device__ __forceinline__ float fsig(float x) {
    return __fdividef(1.0f, 1.0f + __expf(-x));
}
__device__ __forceinline__ float ftanh(float x) {
    return 1.0f - __fdividef(2.0f, __expf(2.0f * x) + 1.0f);
}

__global__ __launch_bounds__(128, 1)
void controller_kernel(const float* __restrict__ w_ih,
                       const float* __restrict__ w_hh,
                       const float* __restrict__ b_ih,
                       const float* __restrict__ b_hh,
                       const float* __restrict__ g_emb,
                       const float* __restrict__ emb_kernel,
                       const float* __restrict__ emb_down,
                       const float* __restrict__ emb_up,
                       const float* __restrict__ w_kernel,
                       const float* __restrict__ w_down,
                       const float* __restrict__ w_up,
                       const float* __restrict__ noise,
                       float* __restrict__ out,
                       int out_size) {
    // Per-warp private x/h copies (each warp recomputes the tail redundantly).
    __shared__ __align__(16) float xh4[4][64];        // [w][0..31]=x, [32..63]=h
    __shared__ float act[2][128];                     // double-buffered gates
    __shared__ float gsh[160];                        // precomputed gumbels
    __shared__ __align__(16) float projsh[3][8 * 36]; // padded stride 36
    __shared__ float embsh[3][8 * 32];
    __shared__ float part_lp[4], part_ent[4];

    const int tid = threadIdx.x;
    const int wid = tid >> 5;
    const int j   = tid & 31;

    // ---- weights for gate-row `tid` into registers ----
    float wr[64];
    {
        const float4* wi4 = (const float4*)w_ih;
        const float4* wh4 = (const float4*)w_hh;
#pragma unroll
        for (int i = 0; i < 8; ++i) {
            float4 a = wi4[tid * 8 + i];
            wr[4 * i + 0] = a.x; wr[4 * i + 1] = a.y;
            wr[4 * i + 2] = a.z; wr[4 * i + 3] = a.w;
            float4 b = wh4[tid * 8 + i];
            wr[32 + 4 * i + 0] = b.x; wr[32 + 4 * i + 1] = b.y;
            wr[32 + 4 * i + 2] = b.z; wr[32 + 4 * i + 3] = b.w;
        }
    }
    const float bias = b_ih[tid] + b_hh[tid];

    // ---- shared-table init ----
    for (int i = tid; i < 3 * 8 * 36; i += 128)
        ((float*)projsh)[i] = 0.0f;
    __syncthreads();
    for (int i = tid; i < 8 * 32; i += 128)
        projsh[0][(i >> 5) * 36 + (i & 31)] = w_kernel[i];
    for (int i = tid; i < 3 * 32; i += 128) {
        projsh[1][(i >> 5) * 36 + (i & 31)] = w_down[i];
        projsh[2][(i >> 5) * 36 + (i & 31)] = w_up[i];
    }
    for (int i = tid; i < 8 * 32; i += 128)
        embsh[0][i] = emb_kernel[i];
    for (int i = tid; i < 3 * 32; i += 128) {
        embsh[1][i] = emb_down[i];
        embsh[2][i] = emb_up[i];
    }
    // gumbels: accurate logf, parallel, off the recurrence path
    for (int i = tid; i < T_STEPS * 8; i += 128) {
        float u = noise[i];
        gsh[i] = -logf(-logf(u * (1.0f - 1e-6f) + 1e-7f));
    }
    // init all 4 private xh copies
    {
        const float x0 = g_emb[j];
        xh4[wid][j] = x0;
        xh4[wid][32 + j] = 0.0f;
    }

    float c = 0.0f;                  // per-warp lane-j cell state (replicated)
    float lp_sum = 0.0f, ent_sum = 0.0f;
    const bool is_sig = (tid < 64) || (tid >= 96);  // warp-uniform

    __syncthreads();

    for (int t = 0; t < T_STEPS; ++t) {
        // ---- matvec: gate row `tid`, reading this warp's private xh ----
        float a0 = bias, a1 = 0.0f, a2 = 0.0f, a3 = 0.0f;
        const float4* x4 = (const float4*)xh4[wid];
#pragma unroll
        for (int i = 0; i < 16; ++i) {
            float4 v = x4[i];
            a0 = fmaf(wr[4 * i + 0], v.x, a0);
            a1 = fmaf(wr[4 * i + 1], v.y, a1);
            a2 = fmaf(wr[4 * i + 2], v.z, a2);
            a3 = fmaf(wr[4 * i + 3], v.w, a3);
        }
        float gacc = (a0 + a1) + (a2 + a3);
        const int tb = t & 1;
        act[tb][tid] = is_sig ? fsig(gacc) : ftanh(gacc);

        __syncthreads();   // the ONLY cross-warp sync per step

        // ================= redundant tail (every warp) =================
        const float gl = gsh[t * 8 + (j & 7)];

        const float ai = act[tb][j];
        const float af = act[tb][j + 32];
        const float ag = act[tb][j + 64];
        const float ao = act[tb][j + 96];
        c = fmaf(af, c, ai * ag);
        const float h = ao * ftanh(c);
        xh4[wid][32 + j] = h;
        __syncwarp();

        int ph, nvalid;
        if (t < 14)      { ph = 0; nvalid = 8; }
        else if (t < 17) { ph = 1; nvalid = 3; }
        else             { ph = 2; nvalid = 3; }

        // logits: lane handles class a=j&7, h-segment seg=j>>3
        const int a = j & 7, seg = j >> 3;
        const float* pr = &projsh[ph][a * 36 + seg * 8];
        const float* hp = &xh4[wid][32 + seg * 8];
        float4 p0 = *(const float4*)(pr);
        float4 p1 = *(const float4*)(pr + 4);
        float4 h0 = *(const float4*)(hp);
        float4 h1 = *(const float4*)(hp + 4);
        float part = p0.x * h0.x + p0.y * h0.y + p0.z * h0.z + p0.w * h0.w
                   + p1.x * h1.x + p1.y * h1.y + p1.z * h1.z + p1.w * h1.w;
        part += __shfl_xor_sync(FULL, part, 8);
        part += __shfl_xor_sync(FULL, part, 16);
        const float logit = (a < nvalid) ? part : NEGV;

        // Gumbel-argmax: each aligned 8-lane group holds all 8 classes,
        // so 3 xor rounds suffice; ballot+ffs gives lowest class on tie.
        float v = logit + gl;
        float vm = v;
        vm = fmaxf(vm, __shfl_xor_sync(FULL, vm, 1));
        vm = fmaxf(vm, __shfl_xor_sync(FULL, vm, 2));
        vm = fmaxf(vm, __shfl_xor_sync(FULL, vm, 4));
        const unsigned bal = __ballot_sync(FULL, v == vm);
        const int s = (__ffs(bal) - 1) & 7;   // lowest class on tie

        // publish next x immediately (critical path)
        xh4[wid][j] = embsh[ph][s * 32 + j];
        __syncwarp();

        // ---- off-path: lp/ent sums, rotated across warps ----
        if (wid == (t & 3)) {
            float se  = __expf(logit);        // masked -> exact +0
            float ss1 = se * logit;           // 0 * -1e9 -> -0
#pragma unroll
            for (int o = 1; o < 8; o <<= 1) {
                se  += __shfl_xor_sync(FULL, se,  o);
                ss1 += __shfl_xor_sync(FULL, ss1, o);
            }
            const float logit_s = __shfl_sync(FULL, logit, s);
            const float lse = __logf(se);
            lp_sum  += logit_s - lse;
            ent_sum += lse - __fdividef(ss1, se);
            if (j == 0) out[2 + t] = (float)s;
        }
    }

    if (j == 0) { part_lp[wid] = lp_sum; part_ent[wid] = ent_sum; }
    __syncthreads();
    if (tid == 0) {
        out[0] = part_lp[0] + part_lp[1] + part_lp[2] + part_lp[3];
        out[1] = part_ent[0] + part_ent[1] + part_ent[2] + part_ent[3];
    }
}

extern "C" void kernel_launch(void* const* d_in, const int* in_sizes, int n_in,
                              void* d_out, int out_size) {
    const float* w_ih       = (const float*)d_in[0];
    const float* w_hh       = (const float*)d_in[1];
    const float* b_ih       = (const float*)d_in[2];
    const float* b_hh       = (const float*)d_in[3];
    const float* g_emb      = (const float*)d_in[4];
    const float* emb_kernel = (const float*)d_in[5];
    const float* emb_down   = (const float*)d_in[6];
    const float* emb_up     = (const float*)d_in[7];
    const float* w_kernel   = (const float*)d_in[8];
    const float* w_down     = (const float*)d_in[9];
    const float* w_up       = (const float*)d_in[10];
    const float* noise      = (const float*)d_in[11];
    float* out = (float*)d_out;

    controller_kernel<<<1, 128>>>(w_ih, w_hh, b_ih, b_hh, g_emb,
                                  emb_kernel, emb_down, emb_up,
                                  w_kernel, w_down, w_up, noise,
                                  out, out_size);
}